// round 16
// baseline (speedup 1.0000x reference)
#include <cuda_runtime.h>
#include <cuda_bf16.h>

// SparseGNNLayer: out = relu(segment_sum(x[cols]*vals, rows) @ W^T + b)
// R11: software-pipelined agg — prefetch next chunk's (col,val) cooperative
// load while broadcasting/gathering the current chunk, and batch all 8 y4
// loads before any FMA. Kills the per-chunk LDG(meta)->SHFL->LDG(y) serial
// latency chain that held issue% at 32.

#define F 32
#define MAX_NODES 100001

__device__ int    g_row_ptr[MAX_NODES + 1];
__device__ float4 g_y4[MAX_NODES * 8];     // y = x @ W^T, [N][32] as float4[N][8]

// Blocks [0, TB): transform, 256 nodes/block, thread-per-node.
// Blocks [TB, ...): row_ptr build, int4 over edges.
__global__ __launch_bounds__(256) void prologue_kernel(
    const float* __restrict__ x,
    const float* __restrict__ W,
    const int*   __restrict__ rows,
    int N, int E, int TB)
{
    if ((int)blockIdx.x < TB) {
        __shared__ float  xs[256 * 33];
        __shared__ float4 Wt4[F * 8];          // Wt4[in*8+o4] = W[4*o4..+3][in]
        int tid  = threadIdx.x;
        int base = blockIdx.x * 256;

        for (int i = tid; i < F * F; i += 256) {
            int o = i >> 5, in = i & 31;
            ((float*)Wt4)[in * F + o] = W[o * F + in];
        }

        const float4* x4 = (const float4*)x;
        #pragma unroll
        for (int k = 0; k < 8; ++k) {
            int f  = k * 256 + tid;
            int ln = f >> 3, in4 = f & 7;
            float4 val = make_float4(0.f, 0.f, 0.f, 0.f);
            if (base + ln < N) val = __ldg(&x4[(long long)(base + ln) * 8 + in4]);
            xs[ln * 33 + in4 * 4 + 0] = val.x;
            xs[ln * 33 + in4 * 4 + 1] = val.y;
            xs[ln * 33 + in4 * 4 + 2] = val.z;
            xs[ln * 33 + in4 * 4 + 3] = val.w;
        }
        __syncthreads();

        float4 acc[8];
        #pragma unroll
        for (int o4 = 0; o4 < 8; ++o4) acc[o4] = make_float4(0.f, 0.f, 0.f, 0.f);
        #pragma unroll
        for (int in = 0; in < F; ++in) {
            float xv = xs[tid * 33 + in];
            #pragma unroll
            for (int o4 = 0; o4 < 8; ++o4) {
                float4 w = Wt4[in * 8 + o4];
                acc[o4].x = fmaf(xv, w.x, acc[o4].x);
                acc[o4].y = fmaf(xv, w.y, acc[o4].y);
                acc[o4].z = fmaf(xv, w.z, acc[o4].z);
                acc[o4].w = fmaf(xv, w.w, acc[o4].w);
            }
        }
        __syncthreads();

        #pragma unroll
        for (int o4 = 0; o4 < 8; ++o4) {
            xs[tid * 33 + o4 * 4 + 0] = acc[o4].x;
            xs[tid * 33 + o4 * 4 + 1] = acc[o4].y;
            xs[tid * 33 + o4 * 4 + 2] = acc[o4].z;
            xs[tid * 33 + o4 * 4 + 3] = acc[o4].w;
        }
        __syncthreads();
        #pragma unroll
        for (int k = 0; k < 8; ++k) {
            int f  = k * 256 + tid;
            int ln = f >> 3, o4 = f & 7;
            if (base + ln < N) {
                float4 v;
                v.x = xs[ln * 33 + o4 * 4 + 0];
                v.y = xs[ln * 33 + o4 * 4 + 1];
                v.z = xs[ln * 33 + o4 * 4 + 2];
                v.w = xs[ln * 33 + o4 * 4 + 3];
                g_y4[(long long)(base + ln) * 8 + o4] = v;
            }
        }
    } else {
        int i  = (blockIdx.x - TB) * 256 + threadIdx.x;
        int n4 = E >> 2;
        if (i >= n4) return;
        const int4* r4 = (const int4*)rows;
        int4 rr  = __ldg(&r4[i]);
        int prev = (i == 0) ? -1 : __ldg(&rows[4 * i - 1]);
        int e = 4 * i;
        for (int q = prev + 1; q <= rr.x; ++q) g_row_ptr[q] = e;
        for (int q = rr.x + 1; q <= rr.y; ++q) g_row_ptr[q] = e + 1;
        for (int q = rr.y + 1; q <= rr.z; ++q) g_row_ptr[q] = e + 2;
        for (int q = rr.z + 1; q <= rr.w; ++q) g_row_ptr[q] = e + 3;
        if (e + 4 >= (E & ~3)) {
            int last = rr.w;
            for (int ee = E & ~3; ee < E; ++ee) {
                int r = __ldg(&rows[ee]);
                for (int q = last + 1; q <= r; ++q) g_row_ptr[q] = ee;
                last = r;
            }
            for (int q = last + 1; q <= N; ++q) g_row_ptr[q] = E;
        }
    }
}

// 8 lanes per row: lane = g*8+t. Group g owns row warpRow*4+g, t = float4 idx.
// Software-pipelined: chunk k+1 metadata LDG issued before chunk k broadcast.
__global__ __launch_bounds__(256) void agg_kernel(
    const int*   __restrict__ cols,
    const float* __restrict__ vals,
    const float* __restrict__ b,
    float*       __restrict__ out,
    int N)
{
    int tid  = threadIdx.x;
    int lane = tid & 31;
    int wid  = tid >> 5;
    int g    = lane >> 3;
    int t    = lane & 7;

    int row = (blockIdx.x * 8 + wid) * 4 + g;

    int s = 0, deg = 0;
    if (row < N) {
        s   = g_row_ptr[row];
        deg = g_row_ptr[row + 1] - s;
    }

    int wmax = deg;
    #pragma unroll
    for (int d = 16; d; d >>= 1)
        wmax = max(wmax, __shfl_xor_sync(0xffffffffu, wmax, d));

    float4 acc = make_float4(0.f, 0.f, 0.f, 0.f);
    int gb = g << 3;

    // Prologue: load chunk 0 metadata.
    int   c_cur = 0;
    float v_cur = 0.0f;
    if (t < deg) {
        c_cur = __ldg(&cols[s + t]);
        v_cur = __ldg(&vals[s + t]);
    }

    for (int base = 0; base < wmax; base += 8) {
        // Prefetch chunk k+1 metadata (independent of everything below).
        int   c_nxt = 0;
        float v_nxt = 0.0f;
        int   nb    = base + 8;
        if (nb + t < deg) {
            c_nxt = __ldg(&cols[s + nb + t]);
            v_nxt = __ldg(&vals[s + nb + t]);
        }

        // Broadcast current chunk.
        int   c0 = __shfl_sync(0xffffffffu, c_cur, gb | 0);
        int   c1 = __shfl_sync(0xffffffffu, c_cur, gb | 1);
        int   c2 = __shfl_sync(0xffffffffu, c_cur, gb | 2);
        int   c3 = __shfl_sync(0xffffffffu, c_cur, gb | 3);
        int   c4 = __shfl_sync(0xffffffffu, c_cur, gb | 4);
        int   c5 = __shfl_sync(0xffffffffu, c_cur, gb | 5);
        int   c6 = __shfl_sync(0xffffffffu, c_cur, gb | 6);
        int   c7 = __shfl_sync(0xffffffffu, c_cur, gb | 7);
        float v0 = __shfl_sync(0xffffffffu, v_cur, gb | 0);
        float v1 = __shfl_sync(0xffffffffu, v_cur, gb | 1);
        float v2 = __shfl_sync(0xffffffffu, v_cur, gb | 2);
        float v3 = __shfl_sync(0xffffffffu, v_cur, gb | 3);
        float v4 = __shfl_sync(0xffffffffu, v_cur, gb | 4);
        float v5 = __shfl_sync(0xffffffffu, v_cur, gb | 5);
        float v6 = __shfl_sync(0xffffffffu, v_cur, gb | 6);
        float v7 = __shfl_sync(0xffffffffu, v_cur, gb | 7);

        // Batch all 8 gathers before any FMA.
        float4 p0 = g_y4[c0 * 8 + t];
        float4 p1 = g_y4[c1 * 8 + t];
        float4 p2 = g_y4[c2 * 8 + t];
        float4 p3 = g_y4[c3 * 8 + t];
        float4 p4 = g_y4[c4 * 8 + t];
        float4 p5 = g_y4[c5 * 8 + t];
        float4 p6 = g_y4[c6 * 8 + t];
        float4 p7 = g_y4[c7 * 8 + t];

        acc.x = fmaf(v0, p0.x, acc.x); acc.y = fmaf(v0, p0.y, acc.y);
        acc.z = fmaf(v0, p0.z, acc.z); acc.w = fmaf(v0, p0.w, acc.w);
        acc.x = fmaf(v1, p1.x, acc.x); acc.y = fmaf(v1, p1.y, acc.y);
        acc.z = fmaf(v1, p1.z, acc.z); acc.w = fmaf(v1, p1.w, acc.w);
        acc.x = fmaf(v2, p2.x, acc.x); acc.y = fmaf(v2, p2.y, acc.y);
        acc.z = fmaf(v2, p2.z, acc.z); acc.w = fmaf(v2, p2.w, acc.w);
        acc.x = fmaf(v3, p3.x, acc.x); acc.y = fmaf(v3, p3.y, acc.y);
        acc.z = fmaf(v3, p3.z, acc.z); acc.w = fmaf(v3, p3.w, acc.w);
        acc.x = fmaf(v4, p4.x, acc.x); acc.y = fmaf(v4, p4.y, acc.y);
        acc.z = fmaf(v4, p4.z, acc.z); acc.w = fmaf(v4, p4.w, acc.w);
        acc.x = fmaf(v5, p5.x, acc.x); acc.y = fmaf(v5, p5.y, acc.y);
        acc.z = fmaf(v5, p5.z, acc.z); acc.w = fmaf(v5, p5.w, acc.w);
        acc.x = fmaf(v6, p6.x, acc.x); acc.y = fmaf(v6, p6.y, acc.y);
        acc.z = fmaf(v6, p6.z, acc.z); acc.w = fmaf(v6, p6.w, acc.w);
        acc.x = fmaf(v7, p7.x, acc.x); acc.y = fmaf(v7, p7.y, acc.y);
        acc.z = fmaf(v7, p7.z, acc.z); acc.w = fmaf(v7, p7.w, acc.w);

        c_cur = c_nxt;
        v_cur = v_nxt;
    }

    if (row < N) {
        float4 bb = __ldg(&((const float4*)b)[t]);
        float4 o;
        o.x = fmaxf(acc.x + bb.x, 0.0f);
        o.y = fmaxf(acc.y + bb.y, 0.0f);
        o.z = fmaxf(acc.z + bb.z, 0.0f);
        o.w = fmaxf(acc.w + bb.w, 0.0f);
        ((float4*)out)[row * 8 + t] = o;
    }
}

extern "C" void kernel_launch(void* const* d_in, const int* in_sizes, int n_in,
                              void* d_out, int out_size) {
    const float* x    = (const float*)d_in[0];
    const int*   rows = (const int*)  d_in[1];
    const int*   cols = (const int*)  d_in[2];
    const float* vals = (const float*)d_in[3];
    const float* W    = (const float*)d_in[4];
    const float* b    = (const float*)d_in[5];
    float* out        = (float*)d_out;

    int N = in_sizes[0] / F;   // 100000
    int E = in_sizes[1];       // 1600000

    int TB = (N + 255) / 256;        // transform blocks (thread-per-node)
    int RB = ((E >> 2) + 255) / 256; // row_ptr blocks (int4)

    prologue_kernel<<<TB + RB, 256>>>(x, W, rows, N, E, TB);
    agg_kernel<<<(N + 31) / 32, 256>>>(cols, vals, b, out, N);
}

// round 17
// speedup vs baseline: 1.0519x; 1.0519x over previous
#include <cuda_runtime.h>
#include <cuda_bf16.h>

// SparseGNNLayer: out = relu(segment_sum(x[cols]*vals, rows) @ W^T + b)
// R11: software-pipelined agg — prefetch next chunk's (col,val) cooperative
// load while broadcasting/gathering the current chunk, and batch all 8 y4
// loads before any FMA. Kills the per-chunk LDG(meta)->SHFL->LDG(y) serial
// latency chain that held issue% at 32.

#define F 32
#define MAX_NODES 100001

__device__ int    g_row_ptr[MAX_NODES + 1];
__device__ float4 g_y4[MAX_NODES * 8];     // y = x @ W^T, [N][32] as float4[N][8]

// Blocks [0, TB): transform, 256 nodes/block, thread-per-node.
// Blocks [TB, ...): row_ptr build, int4 over edges.
__global__ __launch_bounds__(256) void prologue_kernel(
    const float* __restrict__ x,
    const float* __restrict__ W,
    const int*   __restrict__ rows,
    int N, int E, int TB)
{
    if ((int)blockIdx.x < TB) {
        __shared__ float  xs[256 * 33];
        __shared__ float4 Wt4[F * 8];          // Wt4[in*8+o4] = W[4*o4..+3][in]
        int tid  = threadIdx.x;
        int base = blockIdx.x * 256;

        for (int i = tid; i < F * F; i += 256) {
            int o = i >> 5, in = i & 31;
            ((float*)Wt4)[in * F + o] = W[o * F + in];
        }

        const float4* x4 = (const float4*)x;
        #pragma unroll
        for (int k = 0; k < 8; ++k) {
            int f  = k * 256 + tid;
            int ln = f >> 3, in4 = f & 7;
            float4 val = make_float4(0.f, 0.f, 0.f, 0.f);
            if (base + ln < N) val = __ldg(&x4[(long long)(base + ln) * 8 + in4]);
            xs[ln * 33 + in4 * 4 + 0] = val.x;
            xs[ln * 33 + in4 * 4 + 1] = val.y;
            xs[ln * 33 + in4 * 4 + 2] = val.z;
            xs[ln * 33 + in4 * 4 + 3] = val.w;
        }
        __syncthreads();

        float4 acc[8];
        #pragma unroll
        for (int o4 = 0; o4 < 8; ++o4) acc[o4] = make_float4(0.f, 0.f, 0.f, 0.f);
        #pragma unroll
        for (int in = 0; in < F; ++in) {
            float xv = xs[tid * 33 + in];
            #pragma unroll
            for (int o4 = 0; o4 < 8; ++o4) {
                float4 w = Wt4[in * 8 + o4];
                acc[o4].x = fmaf(xv, w.x, acc[o4].x);
                acc[o4].y = fmaf(xv, w.y, acc[o4].y);
                acc[o4].z = fmaf(xv, w.z, acc[o4].z);
                acc[o4].w = fmaf(xv, w.w, acc[o4].w);
            }
        }
        __syncthreads();

        #pragma unroll
        for (int o4 = 0; o4 < 8; ++o4) {
            xs[tid * 33 + o4 * 4 + 0] = acc[o4].x;
            xs[tid * 33 + o4 * 4 + 1] = acc[o4].y;
            xs[tid * 33 + o4 * 4 + 2] = acc[o4].z;
            xs[tid * 33 + o4 * 4 + 3] = acc[o4].w;
        }
        __syncthreads();
        #pragma unroll
        for (int k = 0; k < 8; ++k) {
            int f  = k * 256 + tid;
            int ln = f >> 3, o4 = f & 7;
            if (base + ln < N) {
                float4 v;
                v.x = xs[ln * 33 + o4 * 4 + 0];
                v.y = xs[ln * 33 + o4 * 4 + 1];
                v.z = xs[ln * 33 + o4 * 4 + 2];
                v.w = xs[ln * 33 + o4 * 4 + 3];
                g_y4[(long long)(base + ln) * 8 + o4] = v;
            }
        }
    } else {
        int i  = (blockIdx.x - TB) * 256 + threadIdx.x;
        int n4 = E >> 2;
        if (i >= n4) return;
        const int4* r4 = (const int4*)rows;
        int4 rr  = __ldg(&r4[i]);
        int prev = (i == 0) ? -1 : __ldg(&rows[4 * i - 1]);
        int e = 4 * i;
        for (int q = prev + 1; q <= rr.x; ++q) g_row_ptr[q] = e;
        for (int q = rr.x + 1; q <= rr.y; ++q) g_row_ptr[q] = e + 1;
        for (int q = rr.y + 1; q <= rr.z; ++q) g_row_ptr[q] = e + 2;
        for (int q = rr.z + 1; q <= rr.w; ++q) g_row_ptr[q] = e + 3;
        if (e + 4 >= (E & ~3)) {
            int last = rr.w;
            for (int ee = E & ~3; ee < E; ++ee) {
                int r = __ldg(&rows[ee]);
                for (int q = last + 1; q <= r; ++q) g_row_ptr[q] = ee;
                last = r;
            }
            for (int q = last + 1; q <= N; ++q) g_row_ptr[q] = E;
        }
    }
}

// 8 lanes per row: lane = g*8+t. Group g owns row warpRow*4+g, t = float4 idx.
// Software-pipelined: chunk k+1 metadata LDG issued before chunk k broadcast.
__global__ __launch_bounds__(256) void agg_kernel(
    const int*   __restrict__ cols,
    const float* __restrict__ vals,
    const float* __restrict__ b,
    float*       __restrict__ out,
    int N)
{
    int tid  = threadIdx.x;
    int lane = tid & 31;
    int wid  = tid >> 5;
    int g    = lane >> 3;
    int t    = lane & 7;

    int row = (blockIdx.x * 8 + wid) * 4 + g;

    int s = 0, deg = 0;
    if (row < N) {
        s   = g_row_ptr[row];
        deg = g_row_ptr[row + 1] - s;
    }

    int wmax = deg;
    #pragma unroll
    for (int d = 16; d; d >>= 1)
        wmax = max(wmax, __shfl_xor_sync(0xffffffffu, wmax, d));

    float4 acc = make_float4(0.f, 0.f, 0.f, 0.f);
    int gb = g << 3;

    // Prologue: load chunk 0 metadata.
    int   c_cur = 0;
    float v_cur = 0.0f;
    if (t < deg) {
        c_cur = __ldg(&cols[s + t]);
        v_cur = __ldg(&vals[s + t]);
    }

    for (int base = 0; base < wmax; base += 8) {
        // Prefetch chunk k+1 metadata (independent of everything below).
        int   c_nxt = 0;
        float v_nxt = 0.0f;
        int   nb    = base + 8;
        if (nb + t < deg) {
            c_nxt = __ldg(&cols[s + nb + t]);
            v_nxt = __ldg(&vals[s + nb + t]);
        }

        // Broadcast current chunk.
        int   c0 = __shfl_sync(0xffffffffu, c_cur, gb | 0);
        int   c1 = __shfl_sync(0xffffffffu, c_cur, gb | 1);
        int   c2 = __shfl_sync(0xffffffffu, c_cur, gb | 2);
        int   c3 = __shfl_sync(0xffffffffu, c_cur, gb | 3);
        int   c4 = __shfl_sync(0xffffffffu, c_cur, gb | 4);
        int   c5 = __shfl_sync(0xffffffffu, c_cur, gb | 5);
        int   c6 = __shfl_sync(0xffffffffu, c_cur, gb | 6);
        int   c7 = __shfl_sync(0xffffffffu, c_cur, gb | 7);
        float v0 = __shfl_sync(0xffffffffu, v_cur, gb | 0);
        float v1 = __shfl_sync(0xffffffffu, v_cur, gb | 1);
        float v2 = __shfl_sync(0xffffffffu, v_cur, gb | 2);
        float v3 = __shfl_sync(0xffffffffu, v_cur, gb | 3);
        float v4 = __shfl_sync(0xffffffffu, v_cur, gb | 4);
        float v5 = __shfl_sync(0xffffffffu, v_cur, gb | 5);
        float v6 = __shfl_sync(0xffffffffu, v_cur, gb | 6);
        float v7 = __shfl_sync(0xffffffffu, v_cur, gb | 7);

        // Batch all 8 gathers before any FMA.
        float4 p0 = g_y4[c0 * 8 + t];
        float4 p1 = g_y4[c1 * 8 + t];
        float4 p2 = g_y4[c2 * 8 + t];
        float4 p3 = g_y4[c3 * 8 + t];
        float4 p4 = g_y4[c4 * 8 + t];
        float4 p5 = g_y4[c5 * 8 + t];
        float4 p6 = g_y4[c6 * 8 + t];
        float4 p7 = g_y4[c7 * 8 + t];

        acc.x = fmaf(v0, p0.x, acc.x); acc.y = fmaf(v0, p0.y, acc.y);
        acc.z = fmaf(v0, p0.z, acc.z); acc.w = fmaf(v0, p0.w, acc.w);
        acc.x = fmaf(v1, p1.x, acc.x); acc.y = fmaf(v1, p1.y, acc.y);
        acc.z = fmaf(v1, p1.z, acc.z); acc.w = fmaf(v1, p1.w, acc.w);
        acc.x = fmaf(v2, p2.x, acc.x); acc.y = fmaf(v2, p2.y, acc.y);
        acc.z = fmaf(v2, p2.z, acc.z); acc.w = fmaf(v2, p2.w, acc.w);
        acc.x = fmaf(v3, p3.x, acc.x); acc.y = fmaf(v3, p3.y, acc.y);
        acc.z = fmaf(v3, p3.z, acc.z); acc.w = fmaf(v3, p3.w, acc.w);
        acc.x = fmaf(v4, p4.x, acc.x); acc.y = fmaf(v4, p4.y, acc.y);
        acc.z = fmaf(v4, p4.z, acc.z); acc.w = fmaf(v4, p4.w, acc.w);
        acc.x = fmaf(v5, p5.x, acc.x); acc.y = fmaf(v5, p5.y, acc.y);
        acc.z = fmaf(v5, p5.z, acc.z); acc.w = fmaf(v5, p5.w, acc.w);
        acc.x = fmaf(v6, p6.x, acc.x); acc.y = fmaf(v6, p6.y, acc.y);
        acc.z = fmaf(v6, p6.z, acc.z); acc.w = fmaf(v6, p6.w, acc.w);
        acc.x = fmaf(v7, p7.x, acc.x); acc.y = fmaf(v7, p7.y, acc.y);
        acc.z = fmaf(v7, p7.z, acc.z); acc.w = fmaf(v7, p7.w, acc.w);

        c_cur = c_nxt;
        v_cur = v_nxt;
    }

    if (row < N) {
        float4 bb = __ldg(&((const float4*)b)[t]);
        float4 o;
        o.x = fmaxf(acc.x + bb.x, 0.0f);
        o.y = fmaxf(acc.y + bb.y, 0.0f);
        o.z = fmaxf(acc.z + bb.z, 0.0f);
        o.w = fmaxf(acc.w + bb.w, 0.0f);
        ((float4*)out)[row * 8 + t] = o;
    }
}

extern "C" void kernel_launch(void* const* d_in, const int* in_sizes, int n_in,
                              void* d_out, int out_size) {
    const float* x    = (const float*)d_in[0];
    const int*   rows = (const int*)  d_in[1];
    const int*   cols = (const int*)  d_in[2];
    const float* vals = (const float*)d_in[3];
    const float* W    = (const float*)d_in[4];
    const float* b    = (const float*)d_in[5];
    float* out        = (float*)d_out;

    int N = in_sizes[0] / F;   // 100000
    int E = in_sizes[1];       // 1600000

    int TB = (N + 255) / 256;        // transform blocks (thread-per-node)
    int RB = ((E >> 2) + 255) / 256; // row_ptr blocks (int4)

    prologue_kernel<<<TB + RB, 256>>>(x, W, rows, N, E, TB);
    agg_kernel<<<(N + 31) / 32, 256>>>(cols, vals, b, out, N);
}